// round 5
// baseline (speedup 1.0000x reference)
#include <cuda_runtime.h>

#define N_ENTITY 500000
#define N_REL    32
#define DIM      64
#define NHOP     2
#define N_ITEM   10000
#define N_MEM    32
#define BATCH    4096
#define HIST     50

// Static scratch (allocation-free):
__device__ float g_acc[N_ITEM * DIM];            // 2.56 MB: per-item accumulated emb
__device__ float g_ph[N_ENTITY];                 // 2 MB: entity_emb . w_h
__device__ float g_pt[N_ENTITY];                 // 2 MB: entity_emb . w_t
__device__ float g_pr[N_REL];                    // relation projections
__device__ float g_pi[NHOP * N_ITEM * N_MEM];    // 2.56 MB: normalized attention

__device__ __forceinline__ float warp_sum32(float v) {
    #pragma unroll
    for (int off = 16; off > 0; off >>= 1)
        v += __shfl_xor_sync(0xffffffffu, v, off);
    return v;
}

__device__ __forceinline__ float half_sum16(float v) {
    #pragma unroll
    for (int off = 1; off < 16; off <<= 1)
        v += __shfl_xor_sync(0xffffffffu, v, off);
    return v;
}

// ---------------------------------------------------------------------------
// K0: streaming projection pass (also leaves the f32 table L2-resident).
// Halfwarp (16 lanes, float4) per row; coalesced 256B reads.
// ---------------------------------------------------------------------------
__global__ __launch_bounds__(256, 8)
void project_kernel(const float* __restrict__ entity_emb,
                    const float* __restrict__ relation_emb,
                    const float* __restrict__ W_w)
{
    const int tid  = blockIdx.x * 256 + threadIdx.x;
    const int hw   = tid >> 4;
    const int ll   = tid & 15;
    const int n_hw = (gridDim.x * 256) >> 4;

    const float4 wh = reinterpret_cast<const float4*>(W_w)[ll];
    const float4 wt = reinterpret_cast<const float4*>(W_w)[32 + ll];

    for (int e = hw; e < N_ENTITY; e += n_hw) {
        const float4 v = reinterpret_cast<const float4*>(entity_emb)[e * (DIM / 4) + ll];
        float sh = v.x * wh.x + v.y * wh.y + v.z * wh.z + v.w * wh.w;
        float st = v.x * wt.x + v.y * wt.y + v.z * wt.z + v.w * wt.w;
        #pragma unroll
        for (int off = 1; off < 16; off <<= 1) {
            sh += __shfl_xor_sync(0xffffffffu, sh, off);
            st += __shfl_xor_sync(0xffffffffu, st, off);
        }
        if (ll == 0) { g_ph[e] = sh; g_pt[e] = st; }
    }

    if (blockIdx.x == 0 && threadIdx.x < 32) {
        const float4 wr = reinterpret_cast<const float4*>(W_w)[16 + ll];
        const int half = threadIdx.x >> 4;
        for (int r = half; r < N_REL; r += 2) {
            const float4 v = reinterpret_cast<const float4*>(relation_emb)[r * (DIM / 4) + ll];
            float s = v.x * wr.x + v.y * wr.y + v.z * wr.z + v.w * wr.w;
            #pragma unroll
            for (int off = 1; off < 16; off <<= 1)
                s += __shfl_xor_sync(0xffffffffu, s, off);
            if (ll == 0) g_pr[r] = s;
        }
    }
}

// ---------------------------------------------------------------------------
// K1a: logits + per-hop softmax -> normalized pi. One warp per (hop,item),
// lane = memory slot. All gathers are 4B scalars from L2-resident tables.
// ---------------------------------------------------------------------------
__global__ __launch_bounds__(256)
void attn_weight_kernel(const float* __restrict__ W_b,
                        const int*   __restrict__ heads,
                        const int*   __restrict__ relations,
                        const int*   __restrict__ tails)
{
    const int w    = (blockIdx.x * blockDim.x + threadIdx.x) >> 5;  // (hop,item)
    const int lane = threadIdx.x & 31;
    if (w >= NHOP * N_ITEM) return;

    const int off = w * N_MEM + lane;
    const int hi = heads[off];
    const int ri = relations[off];
    const int ti = tails[off];

    const float logit = g_ph[hi] + g_pr[ri] + g_pt[ti] + W_b[0];
    const float sg = 1.0f / (1.0f + expf(-logit));
    const float ev = expf(sg);                 // sg in (0,1): no max-sub needed
    const float denom = warp_sum32(ev);
    g_pi[off] = ev / denom;
}

// ---------------------------------------------------------------------------
// K1b: pure weighted tail gather, maximum MLP, no phase serialization.
// Block per item. Thread t: memory m = t>>2 (0..63, both hops), quarter
// q = t&3 -> dims [16q,16q+16) as 4 independent LDG.128. 1024 row-loads in
// flight per block. Reduce over the warp's 8 memories by shuffle, then 512
// shared atomics.
// ---------------------------------------------------------------------------
__global__ __launch_bounds__(256)
void item_acc_kernel(const float* __restrict__ entity_emb,
                     const int*   __restrict__ item_ids,
                     const int*   __restrict__ tails)
{
    const int item = blockIdx.x;
    const int tid  = threadIdx.x;
    const int lane = tid & 31;
    const int m    = tid >> 2;      // memory slot 0..63 (hop = m>>5)
    const int q    = tid & 3;       // dim quarter

    __shared__ int   st_s[2 * N_MEM];
    __shared__ float pi_s[2 * N_MEM];
    __shared__ float acc_s[DIM];

    if (tid < 64) {
        // tails layout: [hop][item][mem]; tid = hop*32+mm
        const int hop = tid >> 5, mm = tid & 31;
        const int goff = (hop * N_ITEM + item) * N_MEM + mm;
        st_s[tid] = tails[goff];
        pi_s[tid] = g_pi[goff];
        acc_s[tid] = entity_emb[(long long)item_ids[item] * DIM + tid];
    }
    __syncthreads();

    const float4* ee4 = reinterpret_cast<const float4*>(entity_emb);
    const long long row = (long long)st_s[m] * (DIM / 4);
    const float pi = pi_s[m];

    float4 a0 = ee4[row + q * 4 + 0];
    float4 a1 = ee4[row + q * 4 + 1];
    float4 a2 = ee4[row + q * 4 + 2];
    float4 a3 = ee4[row + q * 4 + 3];

    a0.x *= pi; a0.y *= pi; a0.z *= pi; a0.w *= pi;
    a1.x *= pi; a1.y *= pi; a1.z *= pi; a1.w *= pi;
    a2.x *= pi; a2.y *= pi; a2.z *= pi; a2.w *= pi;
    a3.x *= pi; a3.y *= pi; a3.z *= pi; a3.w *= pi;

    // Reduce across the 8 memories in this warp (lanes sharing lane&3).
    #pragma unroll
    for (int off = 4; off < 32; off <<= 1) {
        a0.x += __shfl_xor_sync(0xffffffffu, a0.x, off);
        a0.y += __shfl_xor_sync(0xffffffffu, a0.y, off);
        a0.z += __shfl_xor_sync(0xffffffffu, a0.z, off);
        a0.w += __shfl_xor_sync(0xffffffffu, a0.w, off);
        a1.x += __shfl_xor_sync(0xffffffffu, a1.x, off);
        a1.y += __shfl_xor_sync(0xffffffffu, a1.y, off);
        a1.z += __shfl_xor_sync(0xffffffffu, a1.z, off);
        a1.w += __shfl_xor_sync(0xffffffffu, a1.w, off);
        a2.x += __shfl_xor_sync(0xffffffffu, a2.x, off);
        a2.y += __shfl_xor_sync(0xffffffffu, a2.y, off);
        a2.z += __shfl_xor_sync(0xffffffffu, a2.z, off);
        a2.w += __shfl_xor_sync(0xffffffffu, a2.w, off);
        a3.x += __shfl_xor_sync(0xffffffffu, a3.x, off);
        a3.y += __shfl_xor_sync(0xffffffffu, a3.y, off);
        a3.z += __shfl_xor_sync(0xffffffffu, a3.z, off);
        a3.w += __shfl_xor_sync(0xffffffffu, a3.w, off);
    }

    if (lane < 4) {
        const int base = 16 * lane;   // lane == q here
        atomicAdd(&acc_s[base +  0], a0.x);
        atomicAdd(&acc_s[base +  1], a0.y);
        atomicAdd(&acc_s[base +  2], a0.z);
        atomicAdd(&acc_s[base +  3], a0.w);
        atomicAdd(&acc_s[base +  4], a1.x);
        atomicAdd(&acc_s[base +  5], a1.y);
        atomicAdd(&acc_s[base +  6], a1.z);
        atomicAdd(&acc_s[base +  7], a1.w);
        atomicAdd(&acc_s[base +  8], a2.x);
        atomicAdd(&acc_s[base +  9], a2.y);
        atomicAdd(&acc_s[base + 10], a2.z);
        atomicAdd(&acc_s[base + 11], a2.w);
        atomicAdd(&acc_s[base + 12], a3.x);
        atomicAdd(&acc_s[base + 13], a3.y);
        atomicAdd(&acc_s[base + 14], a3.z);
        atomicAdd(&acc_s[base + 15], a3.w);
    }
    __syncthreads();

    if (tid < 64)
        g_acc[item * DIM + tid] = acc_s[tid];
}

// ---------------------------------------------------------------------------
// K2: user pooling + scoring. One warp per batch row, halfwarp float4 layout.
// ---------------------------------------------------------------------------
__global__ __launch_bounds__(256)
void user_score_kernel(const float* __restrict__ entity_emb,
                       const int*   __restrict__ records_idx,
                       const int*   __restrict__ items,
                       float*       __restrict__ out)
{
    const int warp = (blockIdx.x * blockDim.x + threadIdx.x) >> 5;
    const int lane = threadIdx.x & 31;
    const int half = lane >> 4;
    const int ll   = lane & 15;
    if (warp >= BATCH) return;

    const int* rec = records_idx + warp * HIST;
    const float4* acc4 = reinterpret_cast<const float4*>(g_acc);

    float4 u = make_float4(0.0f, 0.0f, 0.0f, 0.0f);
    #pragma unroll
    for (int i = 0; i < HIST / 2; ++i) {
        const int idx = rec[2 * i + half];
        const float4 a = acc4[idx * (DIM / 4) + ll];
        u.x += a.x; u.y += a.y; u.z += a.z; u.w += a.w;
    }
    u.x += __shfl_xor_sync(0xffffffffu, u.x, 16);
    u.y += __shfl_xor_sync(0xffffffffu, u.y, 16);
    u.z += __shfl_xor_sync(0xffffffffu, u.z, 16);
    u.w += __shfl_xor_sync(0xffffffffu, u.w, 16);

    const int it = items[warp];
    const float4 p = reinterpret_cast<const float4*>(entity_emb)[it * (DIM / 4) + ll];
    float dot = u.x * p.x + u.y * p.y + u.z * p.z + u.w * p.w;
    dot = half_sum16(dot);

    if (lane == 0)
        out[warp] = 1.0f / (1.0f + expf(-dot));
}

// ---------------------------------------------------------------------------
// Launch
// ---------------------------------------------------------------------------
extern "C" void kernel_launch(void* const* d_in, const int* in_sizes, int n_in,
                              void* d_out, int out_size)
{
    const float* entity_emb   = (const float*)d_in[0];
    const float* relation_emb = (const float*)d_in[1];
    const float* W_w          = (const float*)d_in[2];
    const float* W_b          = (const float*)d_in[3];
    const int*   item_ids     = (const int*)d_in[4];
    const int*   heads        = (const int*)d_in[5];
    const int*   relations    = (const int*)d_in[6];
    const int*   tails        = (const int*)d_in[7];
    const int*   records_idx  = (const int*)d_in[8];
    const int*   items        = (const int*)d_in[9];
    float*       out          = (float*)d_out;

    project_kernel<<<1184, 256>>>(entity_emb, relation_emb, W_w);

    // 20000 (hop,item) warps -> 2500 blocks of 8 warps.
    attn_weight_kernel<<<2500, 256>>>(W_b, heads, relations, tails);

    item_acc_kernel<<<N_ITEM, 256>>>(entity_emb, item_ids, tails);

    const int warps_per_block = 256 / 32;
    const int blocks = (BATCH + warps_per_block - 1) / warps_per_block;
    user_score_kernel<<<blocks, 256>>>(entity_emb, records_idx, items, out);
}

// round 6
// speedup vs baseline: 1.4122x; 1.4122x over previous
#include <cuda_runtime.h>
#include <cuda_fp16.h>

#define N_ENTITY 500000
#define N_REL    32
#define DIM      64
#define NHOP     2
#define N_ITEM   10000
#define N_MEM    32
#define BATCH    4096
#define HIST     50

// Static scratch (allocation-free):
__device__ float g_acc[N_ITEM * DIM];       // 2.56 MB: per-item accumulated embedding
__device__ float g_ph[N_ENTITY];            // 2 MB: entity_emb . w_h
__device__ float g_pt[N_ENTITY];            // 2 MB: entity_emb . w_t
__device__ float g_pr[N_REL];               // relation projections
__device__ uint2 g_eth[N_ENTITY * 16];      // 64 MB: fp16 copy of entity table
                                            // (row = 16 x uint2 = 64 halfs)

__device__ __forceinline__ float warp_sum32(float v) {
    #pragma unroll
    for (int off = 16; off > 0; off >>= 1)
        v += __shfl_xor_sync(0xffffffffu, v, off);
    return v;
}

__device__ __forceinline__ float half_sum16(float v) {
    #pragma unroll
    for (int off = 1; off < 16; off <<= 1)
        v += __shfl_xor_sync(0xffffffffu, v, off);
    return v;
}

// ---------------------------------------------------------------------------
// K0: single streaming pass over the entity table.
// Per row: scalar projections (w_h, w_t) AND fp16 compressed copy.
// f32 reads use __ldcs (evict-first) so the 128MB stream does NOT evict the
// L2-resident fp16 table; the fp16 writes allocate normally and stay hot.
// ---------------------------------------------------------------------------
__global__ __launch_bounds__(256, 8)
void project_kernel(const float* __restrict__ entity_emb,
                    const float* __restrict__ relation_emb,
                    const float* __restrict__ W_w)
{
    const int tid  = blockIdx.x * 256 + threadIdx.x;
    const int hw   = tid >> 4;
    const int ll   = tid & 15;
    const int n_hw = (gridDim.x * 256) >> 4;

    const float4 wh = reinterpret_cast<const float4*>(W_w)[ll];
    const float4 wt = reinterpret_cast<const float4*>(W_w)[32 + ll];

    for (int e = hw; e < N_ENTITY; e += n_hw) {
        const float4 v = __ldcs(&reinterpret_cast<const float4*>(entity_emb)[e * (DIM / 4) + ll]);

        // fp16 compressed row (this is what K1 gathers; keep it in L2)
        const __half2 h01 = __floats2half2_rn(v.x, v.y);
        const __half2 h23 = __floats2half2_rn(v.z, v.w);
        uint2 packed;
        packed.x = *reinterpret_cast<const unsigned int*>(&h01);
        packed.y = *reinterpret_cast<const unsigned int*>(&h23);
        g_eth[e * 16 + ll] = packed;

        float sh = v.x * wh.x + v.y * wh.y + v.z * wh.z + v.w * wh.w;
        float st = v.x * wt.x + v.y * wt.y + v.z * wt.z + v.w * wt.w;
        #pragma unroll
        for (int off = 1; off < 16; off <<= 1) {
            sh += __shfl_xor_sync(0xffffffffu, sh, off);
            st += __shfl_xor_sync(0xffffffffu, st, off);
        }
        if (ll == 0) { g_ph[e] = sh; g_pt[e] = st; }
    }

    // Relation projections: warp 0 of block 0.
    if (blockIdx.x == 0 && threadIdx.x < 32) {
        const float4 wr = reinterpret_cast<const float4*>(W_w)[16 + ll];
        const int half = threadIdx.x >> 4;
        for (int r = half; r < N_REL; r += 2) {
            const float4 v = reinterpret_cast<const float4*>(relation_emb)[r * (DIM / 4) + ll];
            float s = v.x * wr.x + v.y * wr.y + v.z * wr.z + v.w * wr.w;
            #pragma unroll
            for (int off = 1; off < 16; off <<= 1)
                s += __shfl_xor_sync(0xffffffffu, s, off);
            if (ll == 0) g_pr[r] = s;
        }
    }
}

// ---------------------------------------------------------------------------
// K1: per-item attention, both hops fused.
// Phase A: 64 threads compute all 64 logits from L2-resident scalar gathers.
// Phase B: 8 warps gather the 64 fp16 tail rows (128B each) from the
//          L2-resident compressed table. Index streams use __ldcs.
// ---------------------------------------------------------------------------
__global__ __launch_bounds__(256, 8)
void item_acc_kernel(const float* __restrict__ entity_emb,
                     const float* __restrict__ W_b,
                     const int*   __restrict__ item_ids,
                     const int*   __restrict__ heads,
                     const int*   __restrict__ relations,
                     const int*   __restrict__ tails)
{
    const int item = blockIdx.x;
    const int tid  = threadIdx.x;
    const int w    = tid >> 5;
    const int lane = tid & 31;
    const int half = lane >> 4;
    const int ll   = lane & 15;

    __shared__ float ev_s[2 * N_MEM];
    __shared__ int   st_s[2 * N_MEM];
    __shared__ float acc_s[DIM];
    __shared__ float denom_s[2];

    // Phase A: logits for all 64 memories + base embedding load.
    if (tid < 64) {
        const int hop = tid >> 5, mm = tid & 31;
        const int off = (hop * N_ITEM + item) * N_MEM + mm;
        const int hi = __ldcs(&heads[off]);
        const int ri = __ldcs(&relations[off]);
        const int ti = __ldcs(&tails[off]);
        st_s[tid] = ti;
        const float logit = g_ph[hi] + g_pr[ri] + g_pt[ti] + W_b[0];
        const float sg = 1.0f / (1.0f + expf(-logit));
        ev_s[tid] = expf(sg);     // softmax numerator; sg in (0,1), no max-sub needed
        acc_s[tid] = __ldcs(&entity_emb[(long long)item_ids[item] * DIM + tid]);
    }
    __syncthreads();

    // Per-hop softmax denominators.
    if (tid < 64) {
        float v = warp_sum32(ev_s[tid]);
        if ((tid & 31) == 0) denom_s[tid >> 5] = v;
    }
    __syncthreads();

    // Phase B: weighted fp16 tail gather. Warp w -> hop (w>>2), 8 memories
    // (2 per halfwarp x 4). Lane ll holds dims [4ll..4ll+3] (one uint2 = 4 halfs).
    const int hop = w >> 2;
    const int wq  = w & 3;
    const float inv = 1.0f / denom_s[hop];

    float4 a = make_float4(0.0f, 0.0f, 0.0f, 0.0f);
    #pragma unroll
    for (int p = 0; p < 4; ++p) {
        const int m  = hop * N_MEM + wq * 8 + 2 * p + half;
        const int ti = st_s[m];
        const float pi = ev_s[m] * inv;
        const uint2 d = g_eth[ti * 16 + ll];
        const float2 f01 = __half22float2(*reinterpret_cast<const __half2*>(&d.x));
        const float2 f23 = __half22float2(*reinterpret_cast<const __half2*>(&d.y));
        a.x += pi * f01.x;
        a.y += pi * f01.y;
        a.z += pi * f23.x;
        a.w += pi * f23.y;
    }
    a.x += __shfl_xor_sync(0xffffffffu, a.x, 16);
    a.y += __shfl_xor_sync(0xffffffffu, a.y, 16);
    a.z += __shfl_xor_sync(0xffffffffu, a.z, 16);
    a.w += __shfl_xor_sync(0xffffffffu, a.w, 16);
    if (half == 0) {
        atomicAdd(&acc_s[4 * ll + 0], a.x);
        atomicAdd(&acc_s[4 * ll + 1], a.y);
        atomicAdd(&acc_s[4 * ll + 2], a.z);
        atomicAdd(&acc_s[4 * ll + 3], a.w);
    }
    __syncthreads();

    if (tid < 64)
        g_acc[item * DIM + tid] = acc_s[tid];
}

// ---------------------------------------------------------------------------
// K2: user pooling + scoring. One warp per batch row, halfwarp float4 layout.
// ---------------------------------------------------------------------------
__global__ __launch_bounds__(256)
void user_score_kernel(const float* __restrict__ entity_emb,
                       const int*   __restrict__ records_idx,
                       const int*   __restrict__ items,
                       float*       __restrict__ out)
{
    const int warp = (blockIdx.x * blockDim.x + threadIdx.x) >> 5;
    const int lane = threadIdx.x & 31;
    const int half = lane >> 4;
    const int ll   = lane & 15;
    if (warp >= BATCH) return;

    const int* rec = records_idx + warp * HIST;
    const float4* acc4 = reinterpret_cast<const float4*>(g_acc);

    float4 u = make_float4(0.0f, 0.0f, 0.0f, 0.0f);
    #pragma unroll
    for (int i = 0; i < HIST / 2; ++i) {
        const int idx = rec[2 * i + half];
        const float4 a = acc4[idx * (DIM / 4) + ll];
        u.x += a.x; u.y += a.y; u.z += a.z; u.w += a.w;
    }
    u.x += __shfl_xor_sync(0xffffffffu, u.x, 16);
    u.y += __shfl_xor_sync(0xffffffffu, u.y, 16);
    u.z += __shfl_xor_sync(0xffffffffu, u.z, 16);
    u.w += __shfl_xor_sync(0xffffffffu, u.w, 16);

    const int it = items[warp];
    const float4 p = __ldcs(&reinterpret_cast<const float4*>(entity_emb)[it * (DIM / 4) + ll]);
    float dot = u.x * p.x + u.y * p.y + u.z * p.z + u.w * p.w;
    dot = half_sum16(dot);

    if (lane == 0)
        out[warp] = 1.0f / (1.0f + expf(-dot));
}

// ---------------------------------------------------------------------------
// Launch
// ---------------------------------------------------------------------------
extern "C" void kernel_launch(void* const* d_in, const int* in_sizes, int n_in,
                              void* d_out, int out_size)
{
    const float* entity_emb   = (const float*)d_in[0];
    const float* relation_emb = (const float*)d_in[1];
    const float* W_w          = (const float*)d_in[2];
    const float* W_b          = (const float*)d_in[3];
    const int*   item_ids     = (const int*)d_in[4];
    const int*   heads        = (const int*)d_in[5];
    const int*   relations    = (const int*)d_in[6];
    const int*   tails        = (const int*)d_in[7];
    const int*   records_idx  = (const int*)d_in[8];
    const int*   items        = (const int*)d_in[9];
    float*       out          = (float*)d_out;

    project_kernel<<<1184, 256>>>(entity_emb, relation_emb, W_w);

    item_acc_kernel<<<N_ITEM, 256>>>(entity_emb, W_b,
                                     item_ids, heads, relations, tails);

    const int warps_per_block = 256 / 32;
    const int blocks = (BATCH + warps_per_block - 1) / warps_per_block;
    user_score_kernel<<<blocks, 256>>>(entity_emb, records_idx, items, out);
}